// round 1
// baseline (speedup 1.0000x reference)
#include <cuda_runtime.h>
#include <cstdint>

#define RES_  0.16f
#define XMIN_ (-51.2f)
#define YMIN_ (-51.2f)
#define EPSV  1e-5f
#define NEGV  (-1.0e9f)

// Folded parameters (written by setup kernel each launch; deterministic).
__device__ float d_L1[64 * 8];    // per out-channel c: {A,B,C,D, E,F,G, b1f}
__device__ float d_W2t[64 * 64];  // [c][k] = W2[k][c] * s2[c]
__device__ float d_b2f[64];
__device__ int   d_is64;

// Fold BN into weights, collapse duplicated/offset feature columns, detect
// int32-vs-int64 layout of the integer inputs.
__global__ void pfn_setup_kernel(const float* __restrict__ W1, const float* __restrict__ b1,
                                 const float* __restrict__ g1, const float* __restrict__ beta1,
                                 const float* __restrict__ m1, const float* __restrict__ v1,
                                 const float* __restrict__ W2, const float* __restrict__ b2,
                                 const float* __restrict__ g2, const float* __restrict__ beta2,
                                 const float* __restrict__ m2, const float* __restrict__ v2,
                                 const unsigned* __restrict__ coords_words)
{
    int c = threadIdx.x;
    if (c == 0) {
        // int64 little-endian: high word of every value in [0,640) is 0.
        int is64 = 1;
        for (int i = 1; i < 128; i += 2)
            if (coords_words[i] != 0u) { is64 = 0; break; }
        d_is64 = is64;
    }
    if (c < 64) {
        float s1 = g1[c] * rsqrtf(v1[c] + EPSV);
        float w0 = W1[0 * 64 + c], w1 = W1[1 * 64 + c], w2 = W1[2 * 64 + c];
        float w3 = W1[3 * 64 + c], w4 = W1[4 * 64 + c], w5 = W1[5 * 64 + c];
        float w6 = W1[6 * 64 + c], w7 = W1[7 * 64 + c], w8 = W1[8 * 64 + c];
        // feat = [x, y, z, r, xo, yo, zo, xo, yo]; xo = x - xc, yo = y - yc, zo = z - zmean
        d_L1[c * 8 + 0] = (w0 + w4 + w7) * s1;       // coeff of x
        d_L1[c * 8 + 1] = (w1 + w5 + w8) * s1;       // coeff of y
        d_L1[c * 8 + 2] = (w2 + w6) * s1;            // coeff of z
        d_L1[c * 8 + 3] = w3 * s1;                   // coeff of r
        d_L1[c * 8 + 4] = -(w4 + w7) * s1;           // coeff of xc   (per pillar)
        d_L1[c * 8 + 5] = -(w5 + w8) * s1;           // coeff of yc   (per pillar)
        d_L1[c * 8 + 6] = -w6 * s1;                  // coeff of zmean(per pillar)
        d_L1[c * 8 + 7] = (b1[c] - m1[c]) * s1 + beta1[c];
        float s2 = g2[c] * rsqrtf(v2[c] + EPSV);
        d_b2f[c] = (b2[c] - m2[c]) * s2 + beta2[c];
        for (int k = 0; k < 64; k++)
            d_W2t[c * 64 + k] = W2[k * 64 + c] * s2;
    }
}

// One warp per pillar, one lane per point.
__global__ __launch_bounds__(256)
void pfn_main_kernel(const float4* __restrict__ pillars,   // [P*32] float4 (x,y,z,r)
                     const void* __restrict__ coords,      // [P,2] int32 or int64
                     const void* __restrict__ npp,         // [P]   int32 or int64
                     float* __restrict__ out,              // [P,64]
                     int P)
{
    __shared__ float sW2[64 * 64];
    __shared__ float sL1[64 * 8];
    __shared__ float sB2[64];

    int tid = threadIdx.x;
    for (int i = tid; i < 64 * 64 / 4; i += 256)
        ((float4*)sW2)[i] = ((const float4*)d_W2t)[i];
    for (int i = tid; i < 64 * 8 / 4; i += 256)
        ((float4*)sL1)[i] = ((const float4*)d_L1)[i];
    if (tid < 64) sB2[tid] = d_b2f[tid];
    int is64 = d_is64;
    __syncthreads();

    int warp = tid >> 5, lane = tid & 31;
    int pid = blockIdx.x * 8 + warp;
    if (pid >= P) return;

    int cy, cx, npts;
    if (is64) {
        const long long* c64 = (const long long*)coords;
        cy = (int)c64[2 * pid];
        cx = (int)c64[2 * pid + 1];
        npts = (int)((const long long*)npp)[pid];
    } else {
        const int* c32 = (const int*)coords;
        cy = c32[2 * pid];
        cx = c32[2 * pid + 1];
        npts = ((const int*)npp)[pid];
    }
    float xc = ((float)cx + 0.5f) * RES_ + XMIN_;
    float yc = ((float)cy + 0.5f) * RES_ + YMIN_;

    float4 pt = pillars[pid * 32 + lane];   // coalesced 512B per warp
    bool active = lane < npts;

    // z mean over active points (butterfly -> all lanes)
    float zs = active ? pt.z : 0.f;
    #pragma unroll
    for (int off = 16; off; off >>= 1)
        zs += __shfl_xor_sync(0xffffffffu, zs, off);
    float zm = zs / fmaxf((float)npts, 1.0f);

    // Layer 1 (folded): h1[c] = relu(b1f + x*A + y*B + z*C + r*D + xc*E + yc*F + zm*G)
    float h1[64];
    #pragma unroll
    for (int c = 0; c < 64; c++) {
        float4 pA = *(const float4*)&sL1[c * 8];
        float4 pB = *(const float4*)&sL1[c * 8 + 4];
        float t = pB.w;
        t = fmaf(pt.x, pA.x, t);
        t = fmaf(pt.y, pA.y, t);
        t = fmaf(pt.z, pA.z, t);
        t = fmaf(pt.w, pA.w, t);
        t = fmaf(xc, pB.x, t);
        t = fmaf(yc, pB.y, t);
        t = fmaf(zm, pB.z, t);
        h1[c] = fmaxf(t, 0.f);
    }

    // Layer 2 + masked max over lanes. c-loop kept rolled (I$), k-loop unrolled.
    float res0 = 0.f, res1 = 0.f;
    #pragma unroll 1
    for (int c = 0; c < 64; c++) {
        const float4* w = (const float4*)&sW2[c * 64];  // uniform broadcast loads
        float acc[4];
        acc[0] = sB2[c]; acc[1] = 0.f; acc[2] = 0.f; acc[3] = 0.f;
        #pragma unroll
        for (int q = 0; q < 16; q++) {
            float4 wv = w[q];
            acc[q & 3] = fmaf(h1[4 * q + 0], wv.x, acc[q & 3]);
            acc[q & 3] = fmaf(h1[4 * q + 1], wv.y, acc[q & 3]);
            acc[q & 3] = fmaf(h1[4 * q + 2], wv.z, acc[q & 3]);
            acc[q & 3] = fmaf(h1[4 * q + 3], wv.w, acc[q & 3]);
        }
        float s = (acc[0] + acc[1]) + (acc[2] + acc[3]);
        float v = active ? fmaxf(s, 0.f) : NEGV;
        #pragma unroll
        for (int off = 16; off; off >>= 1)
            v = fmaxf(v, __shfl_xor_sync(0xffffffffu, v, off));
        if (c < 32) { if (lane == c)        res0 = v; }
        else        { if (lane == (c - 32)) res1 = v; }
    }

    out[pid * 64 + lane]      = res0;   // coalesced
    out[pid * 64 + 32 + lane] = res1;
}

extern "C" void kernel_launch(void* const* d_in, const int* in_sizes, int n_in,
                              void* d_out, int out_size)
{
    const float* pillars = (const float*)d_in[0];
    const void*  coords  = d_in[1];
    const void*  npp     = d_in[2];
    const float* W1 = (const float*)d_in[3];
    const float* b1 = (const float*)d_in[4];
    const float* g1 = (const float*)d_in[5];
    const float* be1 = (const float*)d_in[6];
    const float* m1 = (const float*)d_in[7];
    const float* v1 = (const float*)d_in[8];
    const float* W2 = (const float*)d_in[9];
    const float* b2 = (const float*)d_in[10];
    const float* g2 = (const float*)d_in[11];
    const float* be2 = (const float*)d_in[12];
    const float* m2 = (const float*)d_in[13];
    const float* v2 = (const float*)d_in[14];

    int P = in_sizes[0] / (32 * 4);

    pfn_setup_kernel<<<1, 64>>>(W1, b1, g1, be1, m1, v1,
                                W2, b2, g2, be2, m2, v2,
                                (const unsigned*)coords);
    pfn_main_kernel<<<(P + 7) / 8, 256>>>((const float4*)pillars, coords, npp,
                                          (float*)d_out, P);
}

// round 7
// speedup vs baseline: 3.2110x; 3.2110x over previous
#include <cuda_runtime.h>
#include <cuda_bf16.h>
#include <cstdint>

#define RES_  0.16f
#define XMIN_ (-51.2f)
#define YMIN_ (-51.2f)
#define EPSV  1e-5f
#define NEGV  (-1.0e9f)
#define NEGB  (-1.0e30f)

// ---------------- folded / split parameters (device globals) ----------------
__device__ float d_L1[64 * 8];             // per ch: {A,B,C,D, E,F,G, b1f}
__device__ float d_b2f[64];                // folded layer-2 bias
__device__ __nv_bfloat16 d_Bhi[64 * 64];   // [c][k] split-hi of folded W2^T
__device__ __nv_bfloat16 d_Blo[64 * 64];   // [c][k] split-lo
__device__ int d_is64;

// ---------------- setup: fold BN, collapse features, split weights ----------------
__global__ void pfn_setup_kernel(const float* __restrict__ W1, const float* __restrict__ b1,
                                 const float* __restrict__ g1, const float* __restrict__ beta1,
                                 const float* __restrict__ m1, const float* __restrict__ v1,
                                 const float* __restrict__ W2, const float* __restrict__ b2,
                                 const float* __restrict__ g2, const float* __restrict__ beta2,
                                 const float* __restrict__ m2, const float* __restrict__ v2,
                                 const unsigned* __restrict__ coords_words)
{
    int c = threadIdx.x;
    if (c == 0) {
        int is64 = 1;
        for (int i = 1; i < 128; i += 2)
            if (coords_words[i] != 0u) { is64 = 0; break; }
        d_is64 = is64;
    }
    if (c < 64) {
        float s1 = g1[c] * rsqrtf(v1[c] + EPSV);
        float w0 = W1[0 * 64 + c], w1 = W1[1 * 64 + c], w2 = W1[2 * 64 + c];
        float w3 = W1[3 * 64 + c], w4 = W1[4 * 64 + c], w5 = W1[5 * 64 + c];
        float w6 = W1[6 * 64 + c], w7 = W1[7 * 64 + c], w8 = W1[8 * 64 + c];
        d_L1[c * 8 + 0] = (w0 + w4 + w7) * s1;
        d_L1[c * 8 + 1] = (w1 + w5 + w8) * s1;
        d_L1[c * 8 + 2] = (w2 + w6) * s1;
        d_L1[c * 8 + 3] = w3 * s1;
        d_L1[c * 8 + 4] = -(w4 + w7) * s1;
        d_L1[c * 8 + 5] = -(w5 + w8) * s1;
        d_L1[c * 8 + 6] = -w6 * s1;
        d_L1[c * 8 + 7] = (b1[c] - m1[c]) * s1 + beta1[c];
        float s2 = g2[c] * rsqrtf(v2[c] + EPSV);
        d_b2f[c] = (b2[c] - m2[c]) * s2 + beta2[c];
        for (int k = 0; k < 64; k++) {
            float w = W2[k * 64 + c] * s2;
            __nv_bfloat16 hi = __float2bfloat16(w);
            float lo = w - __bfloat162float(hi);
            d_Bhi[c * 64 + k] = hi;
            d_Blo[c * 64 + k] = __float2bfloat16(lo);
        }
    }
}

// ---------------- mma / ldmatrix helpers (baseline PTX, sm_80+) ----------------
__device__ __forceinline__ uint32_t smem_u32(const void* p) {
    uint32_t a;
    asm("{ .reg .u64 t; cvta.to.shared.u64 t, %1; cvt.u32.u64 %0, t; }" : "=r"(a) : "l"(p));
    return a;
}
__device__ __forceinline__ void ldsm4(uint32_t* r, uint32_t addr) {
    asm volatile("ldmatrix.sync.aligned.m8n8.x4.shared.b16 {%0,%1,%2,%3}, [%4];"
        : "=r"(r[0]), "=r"(r[1]), "=r"(r[2]), "=r"(r[3]) : "r"(addr));
}
__device__ __forceinline__ void mma16816(float* c, const uint32_t* a, uint32_t b0, uint32_t b1) {
    asm volatile("mma.sync.aligned.m16n8k16.row.col.f32.bf16.bf16.f32 "
        "{%0,%1,%2,%3}, {%4,%5,%6,%7}, {%8,%9}, {%0,%1,%2,%3};"
        : "+f"(c[0]), "+f"(c[1]), "+f"(c[2]), "+f"(c[3])
        : "r"(a[0]), "r"(a[1]), "r"(a[2]), "r"(a[3]), "r"(b0), "r"(b1));
}

// ---------------- smem layout ----------------
// W (swizzled 128B rows): hi 8KB, lo 8KB. A (padded 144B rows): per warp hi 4608 + lo 4608.
#define OFF_WHI 0
#define OFF_WLO 8192
#define OFF_A   16384           /* + wid*9216, hi at +0, lo at +4608 */
#define OFF_L1  53248
#define OFF_B2  55296
#define SMEM_SZ 55552

__global__ __launch_bounds__(128, 4)
void pfn_mma_kernel(const float4* __restrict__ pillars,
                    const void* __restrict__ coords,
                    const void* __restrict__ npp,
                    float* __restrict__ out,
                    int P)
{
    extern __shared__ __align__(1024) char smem[];
    const int tid = threadIdx.x, wid = tid >> 5, lane = tid & 31;
    const uint32_t sbase = smem_u32(smem);

    // Stage split weights into SW128-swizzled rows [n][128B]
    for (int i = tid; i < 2048; i += 128) {
        int n = i >> 5;
        uint32_t off = (uint32_t)(n * 128 + (i & 31) * 4);
        uint32_t sw = off ^ ((off >> 3) & 0x70);
        *(uint32_t*)(smem + OFF_WHI + sw) = ((const uint32_t*)d_Bhi)[i];
        *(uint32_t*)(smem + OFF_WLO + sw) = ((const uint32_t*)d_Blo)[i];
    }
    for (int i = tid; i < 512; i += 128) ((float*)(smem + OFF_L1))[i] = d_L1[i];
    if (tid < 64) ((float*)(smem + OFF_B2))[tid] = d_b2f[tid];
    int is64 = d_is64;
    __syncthreads();

    const float* sL1 = (const float*)(smem + OFF_L1);
    const float* sB2 = (const float*)(smem + OFF_B2);
    char* aPtr = smem + OFF_A + wid * 9216 + lane * 144;   // this lane's A row (hi)
    const uint32_t aBase = sbase + OFF_A + wid * 9216;

    // Per-lane ldmatrix address constants.
    const int l7 = lane & 7;
    const uint32_t preB0 = (uint32_t)(l7 * 128 + ((16 * (lane >> 3)) ^ (l7 << 4)));
    const uint32_t preB1 = preB0 + 64;
    const int rowA = l7 + ((lane >> 3) & 1) * 8;
    const uint32_t preA = (uint32_t)(rowA * 144 + 16 * (lane >> 4));
    const int g = lane >> 2;

    const int gw = blockIdx.x * 4 + wid;
    const int stride = gridDim.x * 4;

    for (int pid = gw; pid < P; pid += stride) {
        int cy, cx, npts;
        if (is64) {
            const long long* c64 = (const long long*)coords;
            cy = (int)c64[2 * (size_t)pid];
            cx = (int)c64[2 * (size_t)pid + 1];
            npts = (int)((const long long*)npp)[pid];
        } else {
            const int* c32 = (const int*)coords;
            cy = c32[2 * pid];
            cx = c32[2 * pid + 1];
            npts = ((const int*)npp)[pid];
        }
        float xc = ((float)cx + 0.5f) * RES_ + XMIN_;
        float yc = ((float)cy + 0.5f) * RES_ + YMIN_;

        float4 pt = pillars[(size_t)pid * 32 + lane];
        bool active = lane < npts;
        float zs = active ? pt.z : 0.f;
        #pragma unroll
        for (int off = 16; off; off >>= 1)
            zs += __shfl_xor_sync(0xffffffffu, zs, off);
        float zm = zs / fmaxf((float)npts, 1.0f);

        __syncwarp();   // previous iteration's ldmatrix reads done before overwrite

        // ---- layer 1 (fp32, folded) -> bf16 hi/lo rows in A smem ----
        uint32_t hw[4], lw[4];
        #pragma unroll
        for (int p = 0; p < 32; p++) {
            float4 A0 = *(const float4*)(sL1 + (2 * p) * 8);
            float4 B0 = *(const float4*)(sL1 + (2 * p) * 8 + 4);
            float4 A1 = *(const float4*)(sL1 + (2 * p + 1) * 8);
            float4 B1 = *(const float4*)(sL1 + (2 * p + 1) * 8 + 4);
            float t0 = B0.w;
            t0 = fmaf(pt.x, A0.x, t0); t0 = fmaf(pt.y, A0.y, t0);
            t0 = fmaf(pt.z, A0.z, t0); t0 = fmaf(pt.w, A0.w, t0);
            t0 = fmaf(xc, B0.x, t0);  t0 = fmaf(yc, B0.y, t0);
            t0 = fmaf(zm, B0.z, t0);
            t0 = fmaxf(t0, 0.f);
            float t1 = B1.w;
            t1 = fmaf(pt.x, A1.x, t1); t1 = fmaf(pt.y, A1.y, t1);
            t1 = fmaf(pt.z, A1.z, t1); t1 = fmaf(pt.w, A1.w, t1);
            t1 = fmaf(xc, B1.x, t1);  t1 = fmaf(yc, B1.y, t1);
            t1 = fmaf(zm, B1.z, t1);
            t1 = fmaxf(t1, 0.f);
            __nv_bfloat162 hb = __floats2bfloat162_rn(t0, t1);   // .x=t0(lo), .y=t1(hi)
            float r0 = t0 - __bfloat162float(hb.x);
            float r1 = t1 - __bfloat162float(hb.y);
            __nv_bfloat162 lb = __floats2bfloat162_rn(r0, r1);
            hw[p & 3] = *(uint32_t*)&hb;
            lw[p & 3] = *(uint32_t*)&lb;
            if ((p & 3) == 3) {
                *(uint4*)(aPtr + (p >> 2) * 16)        = make_uint4(hw[0], hw[1], hw[2], hw[3]);
                *(uint4*)(aPtr + 4608 + (p >> 2) * 16) = make_uint4(lw[0], lw[1], lw[2], lw[3]);
            }
        }
        __syncwarp();

        // ---- load A fragments: [t=2][kk=4] x 4 regs, hi and lo ----
        uint32_t ahi[32], alo[32];
        #pragma unroll
        for (int t = 0; t < 2; t++)
            #pragma unroll
            for (int kk = 0; kk < 4; kk++) {
                uint32_t a = aBase + preA + (uint32_t)(t * 2304 + kk * 32);
                ldsm4(&ahi[(t * 4 + kk) * 4], a);
                ldsm4(&alo[(t * 4 + kk) * 4], a + 4608);
            }

        bool p0 = g < npts, p1 = (g + 8) < npts, p2 = (g + 16) < npts, p3 = (g + 24) < npts;

        // ---- per n-tile: B frags, 24 mma, masked col-max, butterfly, store ----
        #pragma unroll 1
        for (int nt = 0; nt < 8; nt++) {
            uint32_t bh[8], bl[8];
            uint32_t wb = sbase + (uint32_t)(nt * 1024);
            ldsm4(&bh[0], wb + OFF_WHI + preB0);
            ldsm4(&bh[4], wb + OFF_WHI + preB1);
            ldsm4(&bl[0], wb + OFF_WLO + preB0);
            ldsm4(&bl[4], wb + OFF_WLO + preB1);

            float C0[4] = {0.f, 0.f, 0.f, 0.f};
            float C1[4] = {0.f, 0.f, 0.f, 0.f};
            #pragma unroll
            for (int kk = 0; kk < 4; kk++) {
                mma16816(C0, &ahi[kk * 4],        bh[2 * kk], bh[2 * kk + 1]);
                mma16816(C1, &ahi[16 + kk * 4],   bh[2 * kk], bh[2 * kk + 1]);
                mma16816(C0, &ahi[kk * 4],        bl[2 * kk], bl[2 * kk + 1]);
                mma16816(C1, &ahi[16 + kk * 4],   bl[2 * kk], bl[2 * kk + 1]);
                mma16816(C0, &alo[kk * 4],        bh[2 * kk], bh[2 * kk + 1]);
                mma16816(C1, &alo[16 + kk * 4],   bh[2 * kk], bh[2 * kk + 1]);
            }

            // rows: C0[0,1]->g, C0[2,3]->g+8, C1[0,1]->g+16, C1[2,3]->g+24
            float cm0 = fmaxf(fmaxf(p0 ? C0[0] : NEGB, p1 ? C0[2] : NEGB),
                              fmaxf(p2 ? C1[0] : NEGB, p3 ? C1[2] : NEGB));
            float cm1 = fmaxf(fmaxf(p0 ? C0[1] : NEGB, p1 ? C0[3] : NEGB),
                              fmaxf(p2 ? C1[1] : NEGB, p3 ? C1[3] : NEGB));
            #pragma unroll
            for (int d = 4; d <= 16; d <<= 1) {
                cm0 = fmaxf(cm0, __shfl_xor_sync(0xffffffffu, cm0, d));
                cm1 = fmaxf(cm1, __shfl_xor_sync(0xffffffffu, cm1, d));
            }
            if (lane < 4) {
                int col = nt * 8 + lane * 2;
                float2 bb = *(const float2*)(sB2 + col);
                float o0 = (npts > 0) ? fmaxf(cm0 + bb.x, 0.f) : NEGV;
                float o1 = (npts > 0) ? fmaxf(cm1 + bb.y, 0.f) : NEGV;
                *(float2*)(out + (size_t)pid * 64 + col) = make_float2(o0, o1);
            }
        }
    }
}

extern "C" void kernel_launch(void* const* d_in, const int* in_sizes, int n_in,
                              void* d_out, int out_size)
{
    const float* pillars = (const float*)d_in[0];
    const void*  coords  = d_in[1];
    const void*  npp     = d_in[2];
    const float* W1 = (const float*)d_in[3];
    const float* b1 = (const float*)d_in[4];
    const float* g1 = (const float*)d_in[5];
    const float* be1 = (const float*)d_in[6];
    const float* m1 = (const float*)d_in[7];
    const float* v1 = (const float*)d_in[8];
    const float* W2 = (const float*)d_in[9];
    const float* b2 = (const float*)d_in[10];
    const float* g2 = (const float*)d_in[11];
    const float* be2 = (const float*)d_in[12];
    const float* m2 = (const float*)d_in[13];
    const float* v2 = (const float*)d_in[14];

    int P = in_sizes[0] / (32 * 4);

    cudaFuncSetAttribute(pfn_mma_kernel, cudaFuncAttributeMaxDynamicSharedMemorySize, SMEM_SZ);

    pfn_setup_kernel<<<1, 64>>>(W1, b1, g1, be1, m1, v1,
                                W2, b2, g2, be2, m2, v2,
                                (const unsigned*)coords);
    pfn_mma_kernel<<<592, 128, SMEM_SZ>>>((const float4*)pillars, coords, npp,
                                          (float*)d_out, P);
}